// round 2
// baseline (speedup 1.0000x reference)
#include <cuda_runtime.h>
#include <cstdint>

typedef unsigned long long ull;

#define PC_B 512
#define PC_K 32

#define L2E 1.4426950408889634f
#define LN2 0.6931471805599453f

// Inter-kernel value scratch (static device memory: allowed)
__device__ float g_l256[(size_t)PC_B * 256 * PC_K];   // 16 MB
__device__ float g_l32 [(size_t)PC_B * 32  * PC_K];   // 2 MB
__device__ float g_l4  [(size_t)PC_B * 4   * PC_K];   // 256 KB

// ---------------------------------------------------------------------------
// Low-level helpers
// ---------------------------------------------------------------------------
__device__ __forceinline__ float ex2f(float x) {
    float r; asm("ex2.approx.f32 %0, %1;" : "=f"(r) : "f"(x)); return r;
}
__device__ __forceinline__ float lg2f(float x) {
    float r; asm("lg2.approx.f32 %0, %1;" : "=f"(r) : "f"(x)); return r;
}
__device__ __forceinline__ ull pack2(float x) {
    ull r; asm("mov.b64 %0, {%1, %1};" : "=l"(r) : "f"(x)); return r;
}
__device__ __forceinline__ void unpack2(ull v, float& lo, float& hi) {
    asm("mov.b64 {%0, %1}, %2;" : "=f"(lo), "=f"(hi) : "l"(v));
}
__device__ __forceinline__ ull fma2(ull a, ull b, ull c) {
    ull d; asm("fma.rn.f32x2 %0, %1, %2, %3;" : "=l"(d) : "l"(a), "l"(b), "l"(c)); return d;
}
__device__ __forceinline__ void lds2(ull& a, ull& b, uint32_t addr) {
    asm("ld.shared.v2.u64 {%0, %1}, [%2];" : "=l"(a), "=l"(b) : "r"(addr));
}
__device__ __forceinline__ uint32_t s2u(const void* p) {
    return (uint32_t)__cvta_generic_to_shared(p);
}

// Stage one node's 32x32 weight matrix (4KB) into per-warp smem (coalesced).
__device__ __forceinline__ void stage_w(float* dst, const float* __restrict__ src, int lane) {
    const float4* s4 = (const float4*)src;
    float4* d4 = (float4*)dst;
#pragma unroll
    for (int i = 0; i < 8; i++) d4[lane + i * 32] = s4[lane + i * 32];
}

// Stage a [32 rows(b)][64 floats] tile (two leaf vectors, contiguous per row)
// from global, transposed into smem stg[k2*33 + b] (pad 33 -> conflict-light).
__device__ __forceinline__ void stage_x(float* stg, const float* __restrict__ gbase,
                                        size_t rstride, int lane) {
    const int k2b = (lane & 15) * 4;
    const int rofs = lane >> 4;
#pragma unroll
    for (int rr = 0; rr < 32; rr += 2) {
        const int row = rr + rofs;
        float4 v = *(const float4*)(gbase + (size_t)row * rstride + k2b);
        stg[(k2b + 0) * 33 + row] = v.x;
        stg[(k2b + 1) * 33 + row] = v.y;
        stg[(k2b + 2) * 33 + row] = v.z;
        stg[(k2b + 3) * 33 + row] = v.w;
    }
}

// Core: one (node, 32-batch) task per warp, thread = one batch.
//   p[k]   = (inA[k] + inB[k]) * log2(e)
//   m0     = max_k p[k]
//   e[k]   = exp2(p[k] - m0)
//   y[j]   = sum_i e[i] * W[i][j]      (packed f32x2 over output pairs)
//   out[j] = (log2(y[j]) + m0) * ln(2)
__device__ __forceinline__ void node_compute(const float* __restrict__ pA,
                                             const float* __restrict__ pB, int istr,
                                             uint32_t waddr,
                                             float* __restrict__ po, int ostr) {
    float p[32];
#pragma unroll
    for (int k = 0; k < 32; k++) p[k] = (pA[k * istr] + pB[k * istr]) * L2E;

    float r[16];
#pragma unroll
    for (int k = 0; k < 16; k++) r[k] = fmaxf(p[k], p[k + 16]);
#pragma unroll
    for (int k = 0; k < 8; k++) r[k] = fmaxf(r[k], r[k + 8]);
#pragma unroll
    for (int k = 0; k < 4; k++) r[k] = fmaxf(r[k], r[k + 4]);
    r[0] = fmaxf(r[0], r[2]); r[1] = fmaxf(r[1], r[3]);
    const float m0 = fmaxf(r[0], r[1]);

    float e[32];
#pragma unroll
    for (int k = 0; k < 32; k++) e[k] = ex2f(p[k] - m0);

    ull acc[16];
#pragma unroll
    for (int q = 0; q < 16; q++) acc[q] = 0ULL;

#pragma unroll
    for (int i = 0; i < 32; i++) {
        const ull ep = pack2(e[i]);
        const uint32_t ra = waddr + (uint32_t)i * 128u;
#pragma unroll
        for (int q = 0; q < 8; q++) {
            ull w0, w1; lds2(w0, w1, ra + (uint32_t)q * 16u);
            acc[2 * q]     = fma2(ep, w0, acc[2 * q]);
            acc[2 * q + 1] = fma2(ep, w1, acc[2 * q + 1]);
        }
    }

#pragma unroll
    for (int q = 0; q < 16; q++) {
        float y0, y1; unpack2(acc[q], y0, y1);
        po[(2 * q)     * ostr] = (lg2f(y0) + m0) * LN2;
        po[(2 * q + 1) * ostr] = (lg2f(y1) + m0) * LN2;
    }
}

// ---------------------------------------------------------------------------
// Subtree kernel: 8 leaves -> 1 node (3 layers). Block = 128 batches, 8 warps.
// Grid: (IN_F/8 subtrees, 4 batch-groups).
// smem (floats): ping[4*32*128] pong[2*32*128] stg[8*64*33] wbuf[8*1024]
// ---------------------------------------------------------------------------
#define PING_OFF 0
#define PONG_OFF 16384
#define STG_OFF  24576
#define WBUF_OFF 41472
#define SMEM_SUB_FLOATS 49664   // 198656 bytes

template <int IN_F>
__global__ void __launch_bounds__(256, 1)
pc_subtree(const float* __restrict__ in, const float* __restrict__ W,
           float* __restrict__ outp) {
    extern __shared__ float sm[];
    float* ping = sm + PING_OFF;
    float* pong = sm + PONG_OFF;
    float* stg  = sm + STG_OFF;
    float* wbuf = sm + WBUF_OFF;

    const int s   = blockIdx.x;
    const int B0  = blockIdx.y * 128;
    const int tid = threadIdx.x;
    const int w   = tid >> 5, lane = tid & 31;
    float* mystg = stg + w * (64 * 33);
    float* myw   = wbuf + w * 1024;
    const uint32_t myw_s = s2u(myw);

    constexpr int OUT_F = IN_F / 8;

    // ---- layer 0: 4 nodes, 16 tasks (node j, batch-half bh) ----
    {
        const int wb0 = 2048 - IN_F;  // weight offset of layer F = IN_F/2
#pragma unroll
        for (int t = 0; t < 2; t++) {
            const int task = w + t * 8;
            const int j = task >> 2, bh = task & 3;
            stage_w(myw, W + (size_t)(wb0 + s * 4 + j) * 1024, lane);
            const float* gbase = in + ((size_t)(B0 + bh * 32) * IN_F + (size_t)s * 8 + 2 * j) * 32;
            stage_x(mystg, gbase, (size_t)IN_F * 32, lane);
            __syncwarp();
            node_compute(mystg + lane, mystg + 32 * 33 + lane, 33, myw_s,
                         ping + (j * 32) * 128 + bh * 32 + lane, 128);
            __syncwarp();
        }
    }
    __syncthreads();

    // ---- layer 1: 2 nodes, 8 tasks ----
    {
        const int wb1 = 2048 - IN_F / 2;
        const int j = w >> 2, bh = w & 3;
        stage_w(myw, W + (size_t)(wb1 + s * 2 + j) * 1024, lane);
        __syncwarp();
        const float* ip = ping + (2 * j * 32) * 128 + bh * 32 + lane;
        node_compute(ip, ip + 32 * 128, 128, myw_s,
                     pong + (j * 32) * 128 + bh * 32 + lane, 128);
    }
    __syncthreads();

    // ---- layer 2: 1 node, 4 tasks (warps 0-3); out to padded root buf in ping ----
    if (w < 4) {
        const int wb2 = 2048 - IN_F / 4;
        const int bh = w;
        stage_w(myw, W + (size_t)(wb2 + s) * 1024, lane);
        __syncwarp();
        const float* ip = pong + bh * 32 + lane;
        node_compute(ip, ip + 32 * 128, 128, myw_s,
                     ping + bh * 32 + lane, 129);
    }
    __syncthreads();

    // ---- copy root vectors to global (coalesced along k) ----
    for (int idx = tid; idx < 128 * 32; idx += 256) {
        const int bb = idx >> 5, k = idx & 31;
        outp[((size_t)(B0 + bb) * OUT_F + s) * 32 + k] = ping[k * 129 + bb];
    }
}

// ---------------------------------------------------------------------------
// Final kernel: 4 leaves -> root + mixture logsumexp. Grid: 4 blocks.
// smem (floats): root[32*129] pong[2*32*128] stg[8*64*33] wbuf[8*1024]
// ---------------------------------------------------------------------------
#define F_ROOT_OFF 0
#define F_PONG_OFF 4128
#define F_STG_OFF  12320
#define F_WBUF_OFF 29216
#define SMEM_FIN_FLOATS 37408   // 149632 bytes

__global__ void __launch_bounds__(256, 1)
pc_final(const float* __restrict__ in, const float* __restrict__ W,
         const float* __restrict__ mlw, float* __restrict__ outp) {
    extern __shared__ float sm[];
    float* root = sm + F_ROOT_OFF;
    float* pong = sm + F_PONG_OFF;
    float* stg  = sm + F_STG_OFF;
    float* wbuf = sm + F_WBUF_OFF;

    const int B0  = blockIdx.x * 128;
    const int tid = threadIdx.x;
    const int w   = tid >> 5, lane = tid & 31;
    float* mystg = stg + w * (64 * 33);
    float* myw   = wbuf + w * 1024;
    const uint32_t myw_s = s2u(myw);

    // ---- layer F=2: 2 nodes, 8 tasks ----
    {
        const int j = w >> 2, bh = w & 3;
        stage_w(myw, W + (size_t)(2044 + j) * 1024, lane);
        const float* gbase = in + ((size_t)(B0 + bh * 32) * 4 + 2 * j) * 32;
        stage_x(mystg, gbase, (size_t)4 * 32, lane);
        __syncwarp();
        node_compute(mystg + lane, mystg + 32 * 33 + lane, 33, myw_s,
                     pong + (j * 32) * 128 + bh * 32 + lane, 128);
    }
    __syncthreads();

    // ---- layer F=1: root, 4 tasks ----
    if (w < 4) {
        const int bh = w;
        stage_w(myw, W + (size_t)2046 * 1024, lane);
        __syncwarp();
        const float* ip = pong + bh * 32 + lane;
        node_compute(ip, ip + 32 * 128, 128, myw_s, root + bh * 32 + lane, 129);
    }
    __syncthreads();

    // ---- mixture: out[b] = logsumexp(2*root + log_softmax(mlw)) ----
    if (tid < 128) {
        const int b = tid;
        float lw[32];
#pragma unroll
        for (int k = 0; k < 32; k++) lw[k] = mlw[k];
        float m1 = lw[0];
#pragma unroll
        for (int k = 1; k < 32; k++) m1 = fmaxf(m1, lw[k]);
        float s1 = 0.f;
#pragma unroll
        for (int k = 0; k < 32; k++) s1 += ex2f((lw[k] - m1) * L2E);
        const float lse = lg2f(s1) * LN2 + m1;

        float t[32];
#pragma unroll
        for (int k = 0; k < 32; k++)
            t[k] = 2.0f * root[k * 129 + b] + lw[k] - lse;
        float m2 = t[0];
#pragma unroll
        for (int k = 1; k < 32; k++) m2 = fmaxf(m2, t[k]);
        float s2 = 0.f;
#pragma unroll
        for (int k = 0; k < 32; k++) s2 += ex2f((t[k] - m2) * L2E);
        outp[B0 + b] = lg2f(s2) * LN2 + m2;
    }
}

// ---------------------------------------------------------------------------
// Launch. Inputs: x f32[512,2048,32], weights f32[2047,32,32],
// fold_idx i32 (trivial (2f,2f+1) pairing -> computed), mix_logw f32[32].
// Output: f32[512].
// ---------------------------------------------------------------------------
extern "C" void kernel_launch(void* const* d_in, const int* in_sizes, int n_in,
                              void* d_out, int out_size) {
    const float* x   = (const float*)d_in[0];
    const float* W   = (const float*)d_in[1];
    const float* mlw = (const float*)d_in[3];
    float* out = (float*)d_out;

    float* g1; cudaGetSymbolAddress((void**)&g1, g_l256);
    float* g2; cudaGetSymbolAddress((void**)&g2, g_l32);
    float* g3; cudaGetSymbolAddress((void**)&g3, g_l4);

    const int smem_sub = SMEM_SUB_FLOATS * sizeof(float);
    const int smem_fin = SMEM_FIN_FLOATS * sizeof(float);
    cudaFuncSetAttribute(pc_subtree<2048>, cudaFuncAttributeMaxDynamicSharedMemorySize, smem_sub);
    cudaFuncSetAttribute(pc_subtree<256>,  cudaFuncAttributeMaxDynamicSharedMemorySize, smem_sub);
    cudaFuncSetAttribute(pc_subtree<32>,   cudaFuncAttributeMaxDynamicSharedMemorySize, smem_sub);
    cudaFuncSetAttribute(pc_final,         cudaFuncAttributeMaxDynamicSharedMemorySize, smem_fin);

    pc_subtree<2048><<<dim3(256, 4), 256, smem_sub>>>(x,  W, g1);
    pc_subtree<256> <<<dim3(32, 4),  256, smem_sub>>>(g1, W, g2);
    pc_subtree<32>  <<<dim3(4, 4),   256, smem_sub>>>(g2, W, g3);
    pc_final        <<<4,            256, smem_fin>>>(g3, W, mlw, out);
}

// round 3
// speedup vs baseline: 5.1156x; 5.1156x over previous
#include <cuda_runtime.h>
#include <cstdint>

typedef unsigned long long ull;

#define PC_B 512
#define PC_K 32

#define L2E 1.4426950408889634f
#define LN2 0.6931471805599453f

// Inter-kernel value scratch (static device memory: allowed)
__device__ float g_l256[(size_t)PC_B * 256 * PC_K];   // 16 MB
__device__ float g_l32 [(size_t)PC_B * 32  * PC_K];   // 2 MB
__device__ float g_l4  [(size_t)PC_B * 4   * PC_K];   // 256 KB

// ---------------------------------------------------------------------------
// Low-level helpers
// ---------------------------------------------------------------------------
__device__ __forceinline__ float ex2f(float x) {
    float r; asm("ex2.approx.f32 %0, %1;" : "=f"(r) : "f"(x)); return r;
}
__device__ __forceinline__ float lg2f(float x) {
    float r; asm("lg2.approx.f32 %0, %1;" : "=f"(r) : "f"(x)); return r;
}
__device__ __forceinline__ ull pack2(float x) {
    ull r; asm("mov.b64 %0, {%1, %1};" : "=l"(r) : "f"(x)); return r;
}
__device__ __forceinline__ void unpack2(ull v, float& lo, float& hi) {
    asm("mov.b64 {%0, %1}, %2;" : "=f"(lo), "=f"(hi) : "l"(v));
}
__device__ __forceinline__ ull fma2(ull a, ull b, ull c) {
    ull d; asm("fma.rn.f32x2 %0, %1, %2, %3;" : "=l"(d) : "l"(a), "l"(b), "l"(c)); return d;
}
__device__ __forceinline__ void lds2(ull& a, ull& b, uint32_t addr) {
    asm("ld.shared.v2.u64 {%0, %1}, [%2];" : "=l"(a), "=l"(b) : "r"(addr));
}
__device__ __forceinline__ uint32_t s2u(const void* p) {
    return (uint32_t)__cvta_generic_to_shared(p);
}

// Stage one node's 32x32 weight matrix (4KB) into per-warp smem (coalesced).
__device__ __forceinline__ void stage_w(float* dst, const float* __restrict__ src, int lane) {
    const float4* s4 = (const float4*)src;
    float4* d4 = (float4*)dst;
#pragma unroll
    for (int i = 0; i < 8; i++) d4[lane + i * 32] = s4[lane + i * 32];
}

// Stage a [32 rows(b)][64 floats] tile (two sibling leaf vectors per row)
// from global, transposed into smem stg[k2*33 + b] (pad 33 -> conflict-free).
__device__ __forceinline__ void stage_x(float* stg, const float* __restrict__ gbase,
                                        size_t rstride, int lane) {
    const int k2b = (lane & 15) * 4;
    const int rofs = lane >> 4;
#pragma unroll
    for (int rr = 0; rr < 32; rr += 2) {
        const int row = rr + rofs;
        float4 v = *(const float4*)(gbase + (size_t)row * rstride + k2b);
        stg[(k2b + 0) * 33 + row] = v.x;
        stg[(k2b + 1) * 33 + row] = v.y;
        stg[(k2b + 2) * 33 + row] = v.z;
        stg[(k2b + 3) * 33 + row] = v.w;
    }
}

// Core: one (node, 32-batch) task per warp, thread = one batch.
// All values natural log. Max subtracted BEFORE log2 scaling (precision!).
__device__ __forceinline__ void node_compute(const float* __restrict__ pA,
                                             const float* __restrict__ pB, int istr,
                                             uint32_t waddr,
                                             float* __restrict__ po, int ostr) {
    float p[32];
#pragma unroll
    for (int k = 0; k < 32; k++) p[k] = pA[k * istr] + pB[k * istr];

    float m0 = p[0], m1 = p[1], m2 = p[2], m3 = p[3];
#pragma unroll
    for (int k = 4; k < 32; k += 4) {
        m0 = fmaxf(m0, p[k]); m1 = fmaxf(m1, p[k + 1]);
        m2 = fmaxf(m2, p[k + 2]); m3 = fmaxf(m3, p[k + 3]);
    }
    const float mx = fmaxf(fmaxf(m0, m1), fmaxf(m2, m3));
    const float nmx = -mx * L2E;

#pragma unroll
    for (int k = 0; k < 32; k++) p[k] = ex2f(fmaf(p[k], L2E, nmx));  // reuse p as e

    ull acc[16];
#pragma unroll
    for (int q = 0; q < 16; q++) acc[q] = 0ULL;

#pragma unroll 4
    for (int i = 0; i < 32; i++) {
        const ull ep = pack2(p[i]);
        const uint32_t ra = waddr + (uint32_t)i * 128u;
#pragma unroll
        for (int q = 0; q < 8; q++) {
            ull w0, w1; lds2(w0, w1, ra + (uint32_t)q * 16u);
            acc[2 * q]     = fma2(ep, w0, acc[2 * q]);
            acc[2 * q + 1] = fma2(ep, w1, acc[2 * q + 1]);
        }
    }

#pragma unroll
    for (int q = 0; q < 16; q++) {
        float y0, y1; unpack2(acc[q], y0, y1);
        po[(2 * q)     * ostr] = fmaf(lg2f(y0), LN2, mx);
        po[(2 * q + 1) * ostr] = fmaf(lg2f(y1), LN2, mx);
    }
}

// ---------------------------------------------------------------------------
// Subtree kernel: 8 leaves -> 1 node (3 layers). Block = 128 batches, 8 warps.
// Grid: (IN_F/8 subtrees, 4 batch-groups).
// smem (floats): ping[4*32*128] pong[2*32*128] stg[8*64*33] wbuf[8*1024]
// ---------------------------------------------------------------------------
#define PING_OFF 0
#define PONG_OFF 16384
#define STG_OFF  24576
#define WBUF_OFF 41472
#define SMEM_SUB_FLOATS 49664   // 198656 bytes

template <int IN_F>
__global__ void __launch_bounds__(256, 1)
pc_subtree(const float* __restrict__ in, const float* __restrict__ W,
           float* __restrict__ outp) {
    extern __shared__ float sm[];
    float* ping = sm + PING_OFF;
    float* pong = sm + PONG_OFF;
    float* stg  = sm + STG_OFF;
    float* wbuf = sm + WBUF_OFF;

    const int s   = blockIdx.x;
    const int B0  = blockIdx.y * 128;
    const int tid = threadIdx.x;
    const int w   = tid >> 5, lane = tid & 31;
    float* mystg = stg + w * (64 * 33);
    float* myw   = wbuf + w * 1024;
    const uint32_t myw_s = s2u(myw);

    constexpr int OUT_F = IN_F / 8;

    // ---- layer 0: 4 nodes, 16 tasks (node j, batch-quarter bh) ----
    {
        const int wb0 = 2048 - IN_F;
#pragma unroll
        for (int t = 0; t < 2; t++) {
            const int task = w + t * 8;
            const int j = task >> 2, bh = task & 3;
            stage_w(myw, W + (size_t)(wb0 + s * 4 + j) * 1024, lane);
            const float* gbase = in + ((size_t)(B0 + bh * 32) * IN_F + (size_t)s * 8 + 2 * j) * 32;
            stage_x(mystg, gbase, (size_t)IN_F * 32, lane);
            __syncwarp();
            node_compute(mystg + lane, mystg + 32 * 33 + lane, 33, myw_s,
                         ping + (j * 32) * 128 + bh * 32 + lane, 128);
        }
    }
    __syncthreads();

    // ---- layer 1: 2 nodes, 8 tasks ----
    {
        const int wb1 = 2048 - IN_F / 2;
        const int j = w >> 2, bh = w & 3;
        stage_w(myw, W + (size_t)(wb1 + s * 2 + j) * 1024, lane);
        __syncwarp();
        const float* ip = ping + (2 * j * 32) * 128 + bh * 32 + lane;
        node_compute(ip, ip + 32 * 128, 128, myw_s,
                     pong + (j * 32) * 128 + bh * 32 + lane, 128);
    }
    __syncthreads();

    // ---- layer 2: 1 node, 4 tasks; out into padded buffer (stride 129) ----
    if (w < 4) {
        const int wb2 = 2048 - IN_F / 4;
        const int bh = w;
        stage_w(myw, W + (size_t)(wb2 + s) * 1024, lane);
        __syncwarp();
        const float* ip = pong + bh * 32 + lane;
        node_compute(ip, ip + 32 * 128, 128, myw_s,
                     ping + bh * 32 + lane, 129);
    }
    __syncthreads();

    // ---- copy root vectors to global (coalesced along k) ----
    for (int idx = tid; idx < 128 * 32; idx += 256) {
        const int bb = idx >> 5, k = idx & 31;
        outp[((size_t)(B0 + bb) * OUT_F + s) * 32 + k] = ping[k * 129 + bb];
    }
}

// ---------------------------------------------------------------------------
// Tail kernel: F=4 -> root + mixture. Grid: 16 blocks x 128 thr, 32 batches each.
// smem: tr[128*33] (input transpose / reused for root), o2[64*33], wbuf[2*1024], lwbuf[32]
// ---------------------------------------------------------------------------
__global__ void __launch_bounds__(128, 1)
pc_tail4(const float* __restrict__ in, const float* __restrict__ W,
         const float* __restrict__ mlw, float* __restrict__ outp) {
    __shared__ float tr[128 * 33];
    __shared__ float o2[64 * 33];
    __shared__ float wbuf[2 * 1024];
    __shared__ float lwbuf[32];

    const int B0  = blockIdx.x * 32;
    const int tid = threadIdx.x;
    const int w   = tid >> 5, lane = tid & 31;

    if (tid < 32) lwbuf[tid] = mlw[tid];

    // stage input [32 batches][4 nodes * 32 k] transposed: tr[c*33 + b]
    for (int idx = tid; idx < 32 * 128; idx += 128) {
        const int b = idx >> 7, c = idx & 127;
        tr[c * 33 + b] = in[(size_t)(B0 + b) * 128 + c];
    }
    __syncthreads();

    // ---- layer F=2: 2 nodes, warps 0-1 ----
    if (w < 2) {
        float* myw = wbuf + w * 1024;
        stage_w(myw, W + (size_t)(2044 + w) * 1024, lane);
        __syncwarp();
        const float* ip = tr + (2 * w * 32) * 33 + lane;
        node_compute(ip, ip + 32 * 33, 33, s2u(myw),
                     o2 + (w * 32) * 33 + lane, 33);
    }
    __syncthreads();

    // ---- layer F=1: root, warp 0; write root into tr[k*33 + b] ----
    if (w == 0) {
        stage_w(wbuf, W + (size_t)2046 * 1024, lane);
        __syncwarp();
        const float* ip = o2 + lane;
        node_compute(ip, ip + 32 * 33, 33, s2u(wbuf), tr + lane, 33);
    }
    __syncthreads();

    // ---- mixture (loop-based, no big register arrays) ----
    if (tid < 32) {
        const int b = tid;
        float m1 = lwbuf[0];
        for (int k = 1; k < 32; k++) m1 = fmaxf(m1, lwbuf[k]);
        float s1 = 0.f;
        for (int k = 0; k < 32; k++) s1 += ex2f((lwbuf[k] - m1) * L2E);
        const float lse = fmaf(lg2f(s1), LN2, m1);

        float m2 = -1e30f;
        for (int k = 0; k < 32; k++)
            m2 = fmaxf(m2, 2.0f * tr[k * 33 + b] + lwbuf[k] - lse);
        float s2 = 0.f;
        for (int k = 0; k < 32; k++)
            s2 += ex2f((2.0f * tr[k * 33 + b] + lwbuf[k] - lse - m2) * L2E);
        outp[B0 + b] = fmaf(lg2f(s2), LN2, m2);
    }
}

// ---------------------------------------------------------------------------
// Launch. Inputs: x f32[512,2048,32], weights f32[2047,32,32],
// fold_idx i32 (trivial (2f,2f+1) pairing -> computed), mix_logw f32[32].
// Output: f32[512].
// ---------------------------------------------------------------------------
extern "C" void kernel_launch(void* const* d_in, const int* in_sizes, int n_in,
                              void* d_out, int out_size) {
    const float* x   = (const float*)d_in[0];
    const float* W   = (const float*)d_in[1];
    const float* mlw = (const float*)d_in[3];
    float* out = (float*)d_out;

    float* g1; cudaGetSymbolAddress((void**)&g1, g_l256);
    float* g2; cudaGetSymbolAddress((void**)&g2, g_l32);
    float* g3; cudaGetSymbolAddress((void**)&g3, g_l4);

    const int smem_sub = SMEM_SUB_FLOATS * sizeof(float);
    cudaFuncSetAttribute(pc_subtree<2048>, cudaFuncAttributeMaxDynamicSharedMemorySize, smem_sub);
    cudaFuncSetAttribute(pc_subtree<256>,  cudaFuncAttributeMaxDynamicSharedMemorySize, smem_sub);
    cudaFuncSetAttribute(pc_subtree<32>,   cudaFuncAttributeMaxDynamicSharedMemorySize, smem_sub);

    pc_subtree<2048><<<dim3(256, 4), 256, smem_sub>>>(x,  W, g1);
    pc_subtree<256> <<<dim3(32, 4),  256, smem_sub>>>(g1, W, g2);
    pc_subtree<32>  <<<dim3(4, 4),   256, smem_sub>>>(g2, W, g3);
    pc_tail4        <<<16, 128>>>(g3, W, mlw, out);
}

// round 4
// speedup vs baseline: 5.3072x; 1.0375x over previous
#include <cuda_runtime.h>
#include <cstdint>

typedef unsigned long long ull;

#define L2E 1.4426950408889634f
#define LN2 0.6931471805599453f

// Inter-kernel scratch (static device memory: allowed)
__device__ float g_l128[(size_t)512 * 128 * 32];   // 8 MB
__device__ float g_l8 [(size_t)512 * 8 * 32];      // 512 KB

// ---------------------------------------------------------------------------
// Low-level helpers
// ---------------------------------------------------------------------------
__device__ __forceinline__ float ex2f(float x) {
    float r; asm("ex2.approx.f32 %0, %1;" : "=f"(r) : "f"(x)); return r;
}
__device__ __forceinline__ float lg2f(float x) {
    float r; asm("lg2.approx.f32 %0, %1;" : "=f"(r) : "f"(x)); return r;
}
__device__ __forceinline__ ull pack2(float x) {
    ull r; asm("mov.b64 %0, {%1, %1};" : "=l"(r) : "f"(x)); return r;
}
__device__ __forceinline__ void unpack2(ull v, float& lo, float& hi) {
    asm("mov.b64 {%0, %1}, %2;" : "=f"(lo), "=f"(hi) : "l"(v));
}
__device__ __forceinline__ ull fma2(ull a, ull b, ull c) {
    ull d; asm("fma.rn.f32x2 %0, %1, %2, %3;" : "=l"(d) : "l"(a), "l"(b), "l"(c)); return d;
}
__device__ __forceinline__ void lds2(ull& a, ull& b, uint32_t addr) {
    asm("ld.shared.v2.u64 {%0, %1}, [%2];" : "=l"(a), "=l"(b) : "r"(addr));
}
__device__ __forceinline__ uint32_t s2u(const void* p) {
    return (uint32_t)__cvta_generic_to_shared(p);
}

// ---------------------------------------------------------------------------
// Core: thread = one batch, warp task = one (node, 32 batches).
//   p[k] in regs; m = max; e = exp(p-m); y = e @ W (f32x2-packed, W broadcast
//   from smem); out = log(y) + m. Natural-log values throughout; max is
//   subtracted before the log2 scaling (precision).
// ---------------------------------------------------------------------------
__device__ __forceinline__ void node_core(float p[32], uint32_t waddr,
                                          float* po, int ostr) {
    float m0 = p[0], m1 = p[1], m2 = p[2], m3 = p[3];
#pragma unroll
    for (int k = 4; k < 32; k += 4) {
        m0 = fmaxf(m0, p[k]);     m1 = fmaxf(m1, p[k + 1]);
        m2 = fmaxf(m2, p[k + 2]); m3 = fmaxf(m3, p[k + 3]);
    }
    const float mx = fmaxf(fmaxf(m0, m1), fmaxf(m2, m3));
    const float nmx = -mx * L2E;

#pragma unroll
    for (int k = 0; k < 32; k++) p[k] = ex2f(fmaf(p[k], L2E, nmx));  // p -> e

    ull acc[16];
#pragma unroll
    for (int q = 0; q < 16; q++) acc[q] = 0ULL;

#pragma unroll 4
    for (int i = 0; i < 32; i++) {
        const ull ep = pack2(p[i]);
        const uint32_t ra = waddr + (uint32_t)i * 128u;
#pragma unroll
        for (int q = 0; q < 8; q++) {
            ull w0, w1; lds2(w0, w1, ra + (uint32_t)q * 16u);
            acc[2 * q]     = fma2(ep, w0, acc[2 * q]);
            acc[2 * q + 1] = fma2(ep, w1, acc[2 * q + 1]);
        }
    }

#pragma unroll
    for (int q = 0; q < 16; q++) {
        float y0, y1; unpack2(acc[q], y0, y1);
        po[(2 * q)     * ostr] = fmaf(lg2f(y0), LN2, mx);
        po[(2 * q + 1) * ostr] = fmaf(lg2f(y1), LN2, mx);
    }
}

// Layer-0 variant: the two sibling leaf vectors are 64 contiguous floats.
__device__ __forceinline__ void node_g(const float* __restrict__ gp,
                                       uint32_t waddr, float* po, int ostr) {
    float p[32];
    const float4* g4 = (const float4*)gp;
#pragma unroll
    for (int q = 0; q < 8; q++) {
        float4 a = g4[q], bb = g4[q + 8];
        p[4 * q]     = a.x + bb.x; p[4 * q + 1] = a.y + bb.y;
        p[4 * q + 2] = a.z + bb.z; p[4 * q + 3] = a.w + bb.w;
    }
    node_core(p, waddr, po, ostr);
}

// Inner-layer variant: inputs from smem val buffer (element stride istr).
__device__ __forceinline__ void node_s(const float* sa, const float* sb, int istr,
                                       uint32_t waddr, float* po, int ostr) {
    float p[32];
#pragma unroll
    for (int k = 0; k < 32; k++) p[k] = sa[k * istr] + sb[k * istr];
    node_core(p, waddr, po, ostr);
}

// ---------------------------------------------------------------------------
// Tree kernel: 16-leaf subtree -> 1 node (4 layers), in place.
// Block: 8 warps, 64 batches. Grid: (IN_F/16 subtrees, 8 batch-groups).
// smem: val 8 slots x [32k x 64b] = 64KB; wbuf double buffer 2 x 16KB = 32KB.
// Weight prefetch: LDG->regs before compute, STS after -> latency hidden.
// ---------------------------------------------------------------------------
#define SMEM_TREE_FLOATS (8 * 2048 + 2 * 4096)   // 98304 bytes

template <int IN_F>
__global__ void __launch_bounds__(256, 2)
pc_tree(const float* __restrict__ in, const float* __restrict__ W,
        float* __restrict__ outp) {
    extern __shared__ float sm[];
    float* val = sm;                    // 8 x 2048 floats
    float* wb0 = sm + 16384;            // 4 x 1024
    float* wb1 = sm + 20480;            // 4 x 1024

    const int s   = blockIdx.x;
    const int B0  = blockIdx.y * 64;
    const int tid = threadIdx.x;
    const int w = tid >> 5, lane = tid & 31;
    const int bh = w & 1, jj = w >> 1;      // warp task coords
    const int b  = bh * 32 + lane;          // batch column 0..63

    const int o0 = 2048 - IN_F;
    const float* wsrc0 = W + (size_t)(o0 + s * 8) * 1024;
    const float* wsrc1 = wsrc0 + 4 * 1024;
    const float* wsrc2 = W + (size_t)(o0 + IN_F / 2 + s * 4) * 1024;
    const float* wsrc3 = W + (size_t)(o0 + IN_F / 2 + IN_F / 4 + s * 2) * 1024;
    const float* wsrc4 = W + (size_t)(o0 + IN_F / 2 + IN_F / 4 + IN_F / 8 + s) * 1024;

    // prologue: stage round-0 weights (4 matrices)
    {
        const float4* src = (const float4*)wsrc0;
        float4* dst = (float4*)wb0;
#pragma unroll
        for (int i = 0; i < 4; i++) dst[tid + i * 256] = src[tid + i * 256];
    }
    __syncthreads();

    const float* gbase = in + ((size_t)(B0 + b) * IN_F + s * 16) * 32;
    float4 pw[4];

    // ---- round 0: layer0 nodes 0..3 (j=jj, bh) ----
    {
        const float4* src = (const float4*)wsrc1;
#pragma unroll
        for (int i = 0; i < 4; i++) pw[i] = src[tid + i * 256];
    }
    node_g(gbase + jj * 64, s2u(wb0 + jj * 1024), val + jj * 2048 + b, 64);
    {
        float4* dst = (float4*)wb1;
#pragma unroll
        for (int i = 0; i < 4; i++) dst[tid + i * 256] = pw[i];
    }
    __syncthreads();

    // ---- round 1: layer0 nodes 4..7 ----
    {
        const float4* src = (const float4*)wsrc2;
#pragma unroll
        for (int i = 0; i < 4; i++) pw[i] = src[tid + i * 256];
    }
    node_g(gbase + (4 + jj) * 64, s2u(wb1 + jj * 1024), val + (4 + jj) * 2048 + b, 64);
    {
        float4* dst = (float4*)wb0;
#pragma unroll
        for (int i = 0; i < 4; i++) dst[tid + i * 256] = pw[i];
    }
    __syncthreads();

    // ---- round 2: layer1 node j=jj: slots 2j,2j+1 -> 2j ----
    {
        const float4* src = (const float4*)wsrc3;
#pragma unroll
        for (int i = 0; i < 2; i++) pw[i] = src[tid + i * 256];
    }
    node_s(val + (2 * jj) * 2048 + b, val + (2 * jj + 1) * 2048 + b, 64,
           s2u(wb0 + jj * 1024), val + (2 * jj) * 2048 + b, 64);
    {
        float4* dst = (float4*)wb1;
#pragma unroll
        for (int i = 0; i < 2; i++) dst[tid + i * 256] = pw[i];
    }
    __syncthreads();

    // ---- round 3: layer2, warps 0..3: j=jj(0..1): slots 4j,4j+2 -> 4j ----
    pw[0] = ((const float4*)wsrc4)[tid];
    if (w < 4)
        node_s(val + (4 * jj) * 2048 + b, val + (4 * jj + 2) * 2048 + b, 64,
               s2u(wb1 + jj * 1024), val + (4 * jj) * 2048 + b, 64);
    ((float4*)wb0)[tid] = pw[0];
    __syncthreads();

    // ---- round 4: layer3, warps 0..1: slots 0,4 -> 0 ----
    if (w < 2)
        node_s(val + b, val + 4 * 2048 + b, 64, s2u(wb0), val + b, 64);
    __syncthreads();

    // ---- write root (val slot 0, [k*64 + b]) coalesced-ish per-thread rows ----
    constexpr int OUT_F = IN_F / 16;
    {
        const int b2 = tid & 63, qk = tid >> 6;   // qk 0..3, k-range qk*8..+7
        float* op = outp + ((size_t)(B0 + b2) * OUT_F + s) * 32 + qk * 8;
        float4 v0, v1;
        v0.x = val[(qk * 8 + 0) * 64 + b2]; v0.y = val[(qk * 8 + 1) * 64 + b2];
        v0.z = val[(qk * 8 + 2) * 64 + b2]; v0.w = val[(qk * 8 + 3) * 64 + b2];
        v1.x = val[(qk * 8 + 4) * 64 + b2]; v1.y = val[(qk * 8 + 5) * 64 + b2];
        v1.z = val[(qk * 8 + 6) * 64 + b2]; v1.w = val[(qk * 8 + 7) * 64 + b2];
        *(float4*)op = v0; *((float4*)op + 1) = v1;
    }
}

// ---------------------------------------------------------------------------
// Tail: F=8 -> root + mixture. Grid 16 blocks x 256 thr, 32 batches each.
// smem: val 8 x [32k x 32b] = 32KB; all 7 weight matrices = 28KB; lw 32.
// ---------------------------------------------------------------------------
#define SMEM_TAIL_FLOATS (8 * 1024 + 7 * 1024 + 32)

__global__ void __launch_bounds__(256, 2)
pc_tail8(const float* __restrict__ in, const float* __restrict__ W,
         const float* __restrict__ mlw, float* __restrict__ outp) {
    extern __shared__ float sm[];
    float* val = sm;              // 8 x 1024
    float* wb  = sm + 8192;       // 7 x 1024
    float* lw  = sm + 8192 + 7168;

    const int B0  = blockIdx.x * 32;
    const int tid = threadIdx.x;
    const int w = tid >> 5, lane = tid & 31;

    {
        const float4* src = (const float4*)(W + (size_t)2040 * 1024);
        float4* dst = (float4*)wb;
#pragma unroll
        for (int i = 0; i < 7; i++) dst[tid + i * 256] = src[tid + i * 256];
    }
    if (tid < 32) lw[tid] = mlw[tid];
    __syncthreads();

    // layer F=4: warps 0..3: j=w, reads global nodes 2j,2j+1 -> slot j
    if (w < 4) {
        const float* gp = in + ((size_t)(B0 + lane) * 8 + 2 * w) * 32;
        node_g(gp, s2u(wb + w * 1024), val + w * 1024 + lane, 32);
    }
    __syncthreads();

    // layer F=2: warps 0..1: j=w: slots 2j,2j+1 -> 2j
    if (w < 2)
        node_s(val + (2 * w) * 1024 + lane, val + (2 * w + 1) * 1024 + lane, 32,
               s2u(wb + (4 + w) * 1024), val + (2 * w) * 1024 + lane, 32);
    __syncthreads();

    // layer F=1: warp 0: slots 0,2 -> 0
    if (w == 0)
        node_s(val + lane, val + 2 * 1024 + lane, 32,
               s2u(wb + 6 * 1024), val + lane, 32);
    __syncthreads();

    // mixture: out[b] = logsumexp(2*root + log_softmax(mlw))
    if (tid < 32) {
        const int b2 = tid;
        float m1 = lw[0];
        for (int k = 1; k < 32; k++) m1 = fmaxf(m1, lw[k]);
        float s1 = 0.f;
        for (int k = 0; k < 32; k++) s1 += ex2f((lw[k] - m1) * L2E);
        const float lse = fmaf(lg2f(s1), LN2, m1);

        float m2 = -1e30f;
        for (int k = 0; k < 32; k++)
            m2 = fmaxf(m2, 2.f * val[k * 32 + b2] + lw[k] - lse);
        float s2 = 0.f;
        for (int k = 0; k < 32; k++)
            s2 += ex2f((2.f * val[k * 32 + b2] + lw[k] - lse - m2) * L2E);
        outp[B0 + b2] = fmaf(lg2f(s2), LN2, m2);
    }
}

// ---------------------------------------------------------------------------
// Launch. Inputs: x f32[512,2048,32], weights f32[2047,32,32],
// fold_idx i32 (trivial (2f,2f+1) pairing -> computed), mix_logw f32[32].
// Output: f32[512].
// ---------------------------------------------------------------------------
extern "C" void kernel_launch(void* const* d_in, const int* in_sizes, int n_in,
                              void* d_out, int out_size) {
    const float* x   = (const float*)d_in[0];
    const float* W   = (const float*)d_in[1];
    const float* mlw = (const float*)d_in[3];
    float* out = (float*)d_out;

    float* g1; cudaGetSymbolAddress((void**)&g1, g_l128);
    float* g2; cudaGetSymbolAddress((void**)&g2, g_l8);

    const int smem_tree = SMEM_TREE_FLOATS * sizeof(float);
    const int smem_tail = SMEM_TAIL_FLOATS * sizeof(float);
    cudaFuncSetAttribute(pc_tree<2048>, cudaFuncAttributeMaxDynamicSharedMemorySize, smem_tree);
    cudaFuncSetAttribute(pc_tree<128>,  cudaFuncAttributeMaxDynamicSharedMemorySize, smem_tree);
    cudaFuncSetAttribute(pc_tail8,      cudaFuncAttributeMaxDynamicSharedMemorySize, smem_tail);

    pc_tree<2048><<<dim3(128, 8), 256, smem_tree>>>(x,  W, g1);
    pc_tree<128> <<<dim3(8, 8),   256, smem_tree>>>(g1, W, g2);
    pc_tail8     <<<16,           256, smem_tail>>>(g2, W, mlw, out);
}